// round 3
// baseline (speedup 1.0000x reference)
#include <cuda_runtime.h>

// Problem constants
#define Tn   512
#define Bn   512
#define Fn   128
#define H1n  256
#define H2n  128
#define KTOT 384   // F + H1 == H1 + H2 == 384 (both layers share total K)

#define NBLOCKS 96
#define NTHREADS 256

// smem: persistent weight slab [384][128] + A-chunk buffer [64][36]
#define SB_FLOATS (KTOT * 128)
#define SA_FLOATS (64 * 36)
#define SMEM_BYTES ((SB_FLOATS + SA_FLOATS) * 4)

// Persistent device state (no allocations allowed)
__device__ float g_h1[2][Bn * H1n];   // ping-pong h1
__device__ float g_c1[Bn * H1n];      // in-place c1
__device__ float g_h2[2][Bn * H2n];   // ping-pong h2
__device__ float g_c2[Bn * H2n];      // in-place c2

// Grid barrier state. g_bar_epoch grows monotonically across graph replays;
// g_bar_count always returns to 0, so replays are deterministic.
__device__ unsigned g_bar_count = 0;
__device__ unsigned g_bar_epoch = 0;

__device__ __forceinline__ float sigmoidf_(float x) {
    return 1.0f / (1.0f + expf(-x));
}

__device__ __forceinline__ void grid_barrier(unsigned target) {
    __syncthreads();
    if (threadIdx.x == 0) {
        __threadfence();
        unsigned tick = atomicAdd(&g_bar_count, 1u);
        if (tick == NBLOCKS - 1) {
            g_bar_count = 0;
            __threadfence();
            *(volatile unsigned*)&g_bar_epoch = target;
        } else {
            while ((int)(*(volatile unsigned*)&g_bar_epoch - target) < 0) { }
            __threadfence();
        }
    }
    __syncthreads();
}

// ---------------------------------------------------------------------------
// One persistent kernel runs the entire 2-layer LSTM + dense head.
//   blocks [0,64):  layer1 tiles (rb in {0..7}*64, hb in {0..7}*32 of H1)
//   blocks [64,96): layer2 tiles (rb in {0..7}*64, hb in {0..3}*32 of H2)
// Iteration t: L1 computes step t (t<511), L2 computes step t-1 (t>0).
// One grid barrier per iteration. Weight slab (K=384 x 128 interleaved
// z-cols, col = h*4 + gate) lives in smem for the whole kernel.
// ---------------------------------------------------------------------------
__global__ __launch_bounds__(NTHREADS, 1)
void lstm_persistent(const float* __restrict__ inp,
                     const float* __restrict__ W1, const float* __restrict__ U1,
                     const float* __restrict__ b1,
                     const float* __restrict__ W2, const float* __restrict__ U2,
                     const float* __restrict__ b2,
                     const float* __restrict__ Wd1, const float* __restrict__ bd1,
                     const float* __restrict__ Wd2, const float* __restrict__ bd2,
                     float* __restrict__ out) {
    extern __shared__ float smem[];
    float* sB = smem;                 // [384][128], col = h*4 + gate
    float* sA = smem + SB_FLOATS;     // [64][36]

    const int bid = blockIdx.x;
    const int tid = threadIdx.x;
    const int tx  = tid & 15;         // h-pair owner: h = tx*2, tx*2+1
    const int ty  = tid >> 4;         // 4 batch rows each

    const bool is_l1 = (bid < 64);
    const float* Bw;  const float* Bu;  const float* bias;
    float* cptr;
    int Kx, H, rb, hb;
    if (is_l1) {
        Kx = Fn; H = H1n;
        Bw = W1; Bu = U1; bias = b1; cptr = g_c1;
        rb = (bid >> 3) * 64;
        hb = (bid & 7) * 32;
    } else {
        int lb = bid - 64;
        Kx = H1n; H = H2n;
        Bw = W2; Bu = U2; bias = b2; cptr = g_c2;
        rb = (lb >> 2) * 64;
        hb = (lb & 3) * 32;
    }
    const int ldb = 4 * H;

    unsigned base_epoch;
    {
        __shared__ unsigned s_base;
        if (tid == 0) s_base = *(volatile unsigned*)&g_bar_epoch;
        __syncthreads();
        base_epoch = s_base;
    }
    unsigned nbar = 0;

    // ---- one-time: load weight slab into smem (gate-interleaved cols) ----
    for (int idx = tid; idx < KTOT * 128; idx += NTHREADS) {
        int k = idx >> 7;
        int c = idx & 127;
        int h = c >> 2;
        int g = c & 3;
        int j = g * H + hb + h;
        float v = (k < Kx) ? Bw[(size_t)k * ldb + j] : Bu[(size_t)(k - Kx) * ldb + j];
        sB[idx] = v;
    }

    // ---- one-time: zero recurrent state (partitioned across grid) ----
    {
        int gt = bid * NTHREADS + tid;
        int gstride = NBLOCKS * NTHREADS;
        float* p1 = &g_h1[0][0];
        for (int k = gt; k < 2 * Bn * H1n; k += gstride) p1[k] = 0.0f;
        for (int k = gt; k < Bn * H1n; k += gstride) g_c1[k] = 0.0f;
        float* p2 = &g_h2[0][0];
        for (int k = gt; k < 2 * Bn * H2n; k += gstride) p2[k] = 0.0f;
        for (int k = gt; k < Bn * H2n; k += gstride) g_c2[k] = 0.0f;
    }

    // ---- bias registers: 4 gates x 2 h ----
    float bi[2], bf[2], bg[2], bo[2];
#pragma unroll
    for (int p = 0; p < 2; p++) {
        int h = hb + tx * 2 + p;
        bi[p] = bias[h];
        bf[p] = bias[H + h];
        bg[p] = bias[2 * H + h];
        bo[p] = bias[3 * H + h];
    }

    grid_barrier(base_epoch + (++nbar));   // state zeroed, weights loaded

    for (int t = 0; t < Tn; t++) {
        const int par = t & 1;
        const bool active = is_l1 ? (t < Tn - 1) : (t > 0);

        if (active) {
            const float *Ax, *Ah;
            int lda_x, lda_h;
            float* hout;
            if (is_l1) {
                Ax = inp + (size_t)(t + 1) * Bn * Fn;   // x_{t} = inp[t+1]
                lda_x = Fn;
                Ah = g_h1[par];  lda_h = H1n;
                hout = g_h1[par ^ 1];
            } else {
                Ax = g_h1[par];  lda_x = H1n;
                Ah = g_h2[par];  lda_h = H2n;
                hout = g_h2[par ^ 1];
            }

            float acc[4][8];
#pragma unroll
            for (int i = 0; i < 4; i++)
#pragma unroll
                for (int j = 0; j < 8; j++) acc[i][j] = 0.0f;

            for (int kk = 0; kk < KTOT; kk += 32) {
                const float* Asrc;
                int lda, kbase;
                if (kk < Kx) { Asrc = Ax; lda = lda_x; kbase = kk; }
                else         { Asrc = Ah; lda = lda_h; kbase = kk - Kx; }
#pragma unroll
                for (int rep = 0; rep < 2; rep++) {
                    int v = tid + NTHREADS * rep;      // [0,512)
                    int row = v >> 3;
                    int kq  = (v & 7) << 2;
                    float4 av = *(const float4*)(Asrc + (size_t)(rb + row) * lda + kbase + kq);
                    *(float4*)(sA + row * 36 + kq) = av;
                }
                __syncthreads();

                const float* Bp = sB + (size_t)kk * 128 + tx * 8;
#pragma unroll
                for (int kc = 0; kc < 32; kc++) {
                    float a[4];
#pragma unroll
                    for (int i = 0; i < 4; i++) a[i] = sA[(ty * 4 + i) * 36 + kc];
                    float4 b0 = *(const float4*)(Bp + kc * 128);
                    float4 b1 = *(const float4*)(Bp + kc * 128 + 4);
                    float b[8] = {b0.x, b0.y, b0.z, b0.w, b1.x, b1.y, b1.z, b1.w};
#pragma unroll
                    for (int i = 0; i < 4; i++)
#pragma unroll
                        for (int j = 0; j < 8; j++)
                            acc[i][j] = fmaf(a[i], b[j], acc[i][j]);
                }
                __syncthreads();
            }

            // ---- gate combine entirely in registers; float2 state I/O ----
#pragma unroll
            for (int i = 0; i < 4; i++) {
                int row = rb + ty * 4 + i;
                size_t gbase = (size_t)row * H + hb + tx * 2;
                float2 cold = *(const float2*)(cptr + gbase);
                float cres[2], hres[2];
#pragma unroll
                for (int p = 0; p < 2; p++) {
                    float zi = acc[i][p * 4 + 0] + bi[p];
                    float zf = acc[i][p * 4 + 1] + bf[p];
                    float zg = acc[i][p * 4 + 2] + bg[p];
                    float zo = acc[i][p * 4 + 3] + bo[p];
                    float ig = sigmoidf_(zi);
                    float fg = sigmoidf_(zf);
                    float gg = tanhf(zg);
                    float og = sigmoidf_(zo);
                    float co = (p == 0) ? cold.x : cold.y;
                    float cn = fg * co + ig * gg;
                    cres[p] = cn;
                    hres[p] = og * tanhf(cn);
                }
                *(float2*)(cptr + gbase) = make_float2(cres[0], cres[1]);
                *(float2*)(((float*)0 == 0 ? (is_l1 ? g_h1[par ^ 1] : g_h2[par ^ 1]) : 0) + gbase)
                    = make_float2(hres[0], hres[1]);
            }
        }

        grid_barrier(base_epoch + (++nbar));
    }

    // ---- dense head: blocks 0..3, final h2 lives in g_h2[0] ----
    if (bid < 4) {
        // reuse sB region for Wd1 (128 x 50) + bd1 + Wd2
        float* sWd1 = sB;
        float* sbd1 = sB + H2n * 50;
        float* sWd2 = sbd1 + 50;
        for (int i = tid; i < H2n * 50; i += NTHREADS) sWd1[i] = Wd1[i];
        if (tid < 50) { sbd1[tid] = bd1[tid]; sWd2[tid] = Wd2[tid]; }
        __syncthreads();

        if (tid < 128) {
            int b = bid * 128 + tid;
            const float* hrow = g_h2[0] + (size_t)b * H2n;
            float accj[50];
#pragma unroll
            for (int j = 0; j < 50; j++) accj[j] = 0.0f;
            for (int k = 0; k < H2n; k++) {
                float hv = hrow[k];
                const float* wrow = sWd1 + k * 50;
#pragma unroll
                for (int j = 0; j < 50; j++) accj[j] = fmaf(hv, wrow[j], accj[j]);
            }
            float o = bd2[0];
#pragma unroll
            for (int j = 0; j < 50; j++) o += (accj[j] + sbd1[j]) * sWd2[j];
            out[b] = o;
        }
    }
}

// ---------------------------------------------------------------------------
// kernel_launch: a single persistent kernel launch.
// ---------------------------------------------------------------------------
extern "C" void kernel_launch(void* const* d_in, const int* in_sizes, int n_in,
                              void* d_out, int out_size) {
    const float* inp = (const float*)d_in[0];
    const float* W1  = (const float*)d_in[1];
    const float* U1  = (const float*)d_in[2];
    const float* b1  = (const float*)d_in[3];
    const float* W2  = (const float*)d_in[4];
    const float* U2  = (const float*)d_in[5];
    const float* b2  = (const float*)d_in[6];
    const float* Wd1 = (const float*)d_in[7];
    const float* bd1 = (const float*)d_in[8];
    const float* Wd2 = (const float*)d_in[9];
    const float* bd2 = (const float*)d_in[10];

    static bool attr_done = false;
    if (!attr_done) {
        cudaFuncSetAttribute(lstm_persistent,
                             cudaFuncAttributeMaxDynamicSharedMemorySize,
                             SMEM_BYTES);
        attr_done = true;
    }

    lstm_persistent<<<NBLOCKS, NTHREADS, SMEM_BYTES>>>(
        inp, W1, U1, b1, W2, U2, b2, Wd1, bd1, Wd2, bd2, (float*)d_out);
}

// round 8
// speedup vs baseline: 2.0636x; 2.0636x over previous
#include <cuda_runtime.h>
#include <cstdint>

// Problem constants
#define Tn   512
#define Bn   512
#define Fn   128
#define H1n  256
#define H2n  128
#define KTOT 384

#define NBLOCKS  96
#define NTHREADS 256

// smem layout (floats). B: [KTOT][72] (64 cols + 8 pad -> conflict-free frag
// loads). A: [128][132] (128 K-chunk + 4 pad). Bias: 64.
#define SB_STRIDE 72
#define SA_STRIDE 132
#define OFF_B    0
#define OFF_A    (KTOT * SB_STRIDE)                 // 27648
#define OFF_BIAS (OFF_A + 128 * SA_STRIDE)          // 44544
#define SMEM_FLOATS (OFF_BIAS + 64)
#define SMEM_BYTES  (SMEM_FLOATS * 4)               // ~178 KB

// Persistent device state
__device__ float g_h1[2][Bn * H1n];
__device__ float g_c1[Bn * H1n];
__device__ float g_h2[2][Bn * H2n];
__device__ float g_c2[Bn * H2n];

__device__ unsigned g_bar_count = 0;
__device__ unsigned g_bar_epoch = 0;

__device__ __forceinline__ float sigm_(float x) { return 1.0f / (1.0f + expf(-x)); }

// tf32 round: PTX cvt.rna.tf32.f32 takes a .b32 destination register.
__device__ __forceinline__ float to_tf32(float x) {
    uint32_t y;
    asm("cvt.rna.tf32.f32 %0, %1;" : "=r"(y) : "f"(x));
    return __uint_as_float(y);
}

// D[m16,n8] += A[m16,k8] * B[k8,n8], tf32 inputs (fp32 containers), fp32 accum
__device__ __forceinline__ void mma_tf32(float4& d, const float* a, const float* b) {
    asm volatile(
        "mma.sync.aligned.m16n8k8.row.col.f32.tf32.tf32.f32 "
        "{%0,%1,%2,%3}, {%4,%5,%6,%7}, {%8,%9}, {%0,%1,%2,%3};"
        : "+f"(d.x), "+f"(d.y), "+f"(d.z), "+f"(d.w)
        : "r"(__float_as_uint(a[0])), "r"(__float_as_uint(a[1])),
          "r"(__float_as_uint(a[2])), "r"(__float_as_uint(a[3])),
          "r"(__float_as_uint(b[0])), "r"(__float_as_uint(b[1])));
}

__device__ __forceinline__ void grid_barrier(unsigned target) {
    __syncthreads();
    if (threadIdx.x == 0) {
        __threadfence();
        unsigned tick = atomicAdd(&g_bar_count, 1u);
        if (tick == NBLOCKS - 1) {
            g_bar_count = 0;
            __threadfence();
            *(volatile unsigned*)&g_bar_epoch = target;
        } else {
            while ((int)(*(volatile unsigned*)&g_bar_epoch - target) < 0) { }
            __threadfence();
        }
    }
    __syncthreads();
}

// ---------------------------------------------------------------------------
// Persistent tf32-MMA LSTM.
//  blocks [0,64):  L1 — rb=(bid>>4)*128, hb=(bid&15)*16 of H1
//  blocks [64,96): L2 — rb=(lb>>3)*128,  hb=(lb&7)*16 of H2
// Per step per block: D[128,64] = A[128,384] x B[384,64] via mma.sync tf32.
// Warp grid 4(m) x 2(n); warp tile 32x32 = 2 m-tiles x 4 n-tiles of m16n8.
// z-col n = h*4 + gate -> epilogue needs only one shfl.xor(1) exchange.
// ---------------------------------------------------------------------------
__global__ __launch_bounds__(NTHREADS, 1)
void lstm_mma(const float* __restrict__ inp,
              const float* __restrict__ W1, const float* __restrict__ U1,
              const float* __restrict__ b1,
              const float* __restrict__ W2, const float* __restrict__ U2,
              const float* __restrict__ b2,
              const float* __restrict__ Wd1, const float* __restrict__ bd1,
              const float* __restrict__ Wd2, const float* __restrict__ bd2,
              float* __restrict__ out) {
    extern __shared__ float smem[];
    float* sB = smem + OFF_B;
    float* sA = smem + OFF_A;
    float* sBias = smem + OFF_BIAS;

    const int bid = blockIdx.x;
    const int tid = threadIdx.x;
    const int wid = tid >> 5;
    const int lane = tid & 31;
    const int g = lane >> 2;       // groupID 0..7
    const int tig = lane & 3;      // thread-in-group
    const int wm = wid >> 1;       // warp m-index 0..3
    const int wn = wid & 1;        // warp n-index 0..1

    const bool is_l1 = (bid < 64);
    const float *Bw, *Bu, *bias;
    float* cptr;
    int Kx, H, rb, hb;
    if (is_l1) {
        Kx = Fn; H = H1n; Bw = W1; Bu = U1; bias = b1; cptr = g_c1;
        rb = (bid >> 4) * 128;
        hb = (bid & 15) * 16;
    } else {
        int lb = bid - 64;
        Kx = H1n; H = H2n; Bw = W2; Bu = U2; bias = b2; cptr = g_c2;
        rb = (lb >> 3) * 128;
        hb = (lb & 7) * 16;
    }
    const int ldb = 4 * H;

    // ---- one-time: weights -> smem (tf32-rounded, interleaved cols) ----
    // col n = h*4 + gate  ->  global j = gate*H + hb + h
    for (int idx = tid; idx < 64 * KTOT; idx += NTHREADS) {
        int n = idx / KTOT;
        int k = idx - n * KTOT;
        int j = (n & 3) * H + hb + (n >> 2);
        float v = (k < Kx) ? Bw[(size_t)k * ldb + j] : Bu[(size_t)(k - Kx) * ldb + j];
        sB[k * SB_STRIDE + n] = to_tf32(v);
    }
    if (tid < 64) sBias[tid] = bias[(tid & 3) * H + hb + (tid >> 2)];

    // ---- one-time: zero recurrent state ----
    {
        int gt = bid * NTHREADS + tid;
        int gs = NBLOCKS * NTHREADS;
        float* p1 = &g_h1[0][0];
        for (int k = gt; k < 2 * Bn * H1n; k += gs) p1[k] = 0.0f;
        for (int k = gt; k < Bn * H1n; k += gs) g_c1[k] = 0.0f;
        float* p2 = &g_h2[0][0];
        for (int k = gt; k < 2 * Bn * H2n; k += gs) p2[k] = 0.0f;
        for (int k = gt; k < Bn * H2n; k += gs) g_c2[k] = 0.0f;
    }

    unsigned base_epoch;
    {
        __shared__ unsigned s_base;
        if (tid == 0) s_base = *(volatile unsigned*)&g_bar_epoch;
        __syncthreads();
        base_epoch = s_base;
    }
    unsigned nbar = 0;

    grid_barrier(base_epoch + (++nbar));

    for (int t = 0; t < Tn; t++) {
        const int par = t & 1;
        const bool active = is_l1 ? (t < Tn - 1) : (t > 0);

        if (active) {
            const float *Ax, *Ah;
            int lda_x, lda_h;
            float* hout;
            if (is_l1) {
                Ax = inp + (size_t)(t + 1) * Bn * Fn; lda_x = Fn;
                Ah = g_h1[par]; lda_h = H1n;
                hout = g_h1[par ^ 1];
            } else {
                Ax = g_h1[par]; lda_x = H1n;
                Ah = g_h2[par]; lda_h = H2n;
                hout = g_h2[par ^ 1];
            }

            float4 acc[2][4];
#pragma unroll
            for (int mt = 0; mt < 2; mt++)
#pragma unroll
                for (int nt = 0; nt < 4; nt++)
                    acc[mt][nt] = make_float4(0.f, 0.f, 0.f, 0.f);

            for (int chunk = 0; chunk < 3; chunk++) {
                const int kk = chunk * 128;
                const float* src; int lda, kb;
                if (kk < Kx) { src = Ax; lda = lda_x; kb = kk; }
                else         { src = Ah; lda = lda_h; kb = kk - Kx; }

                // ---- stage A chunk: 128 rows x 128 K, tf32-rounded ----
#pragma unroll
                for (int i = 0; i < 16; i++) {
                    int v = tid + NTHREADS * i;
                    int row = v >> 5;
                    int c4  = v & 31;
                    float4 f = *(const float4*)(src + (size_t)(rb + row) * lda + kb + c4 * 4);
                    f.x = to_tf32(f.x); f.y = to_tf32(f.y);
                    f.z = to_tf32(f.z); f.w = to_tf32(f.w);
                    *(float4*)(sA + row * SA_STRIDE + c4 * 4) = f;
                }
                __syncthreads();

                // ---- 16 K-steps of m16n8k8 ----
#pragma unroll
                for (int ks = 0; ks < 16; ks++) {
                    float a[2][4];
#pragma unroll
                    for (int mt = 0; mt < 2; mt++) {
                        int base = (wm * 32 + mt * 16 + g) * SA_STRIDE + ks * 8 + tig;
                        a[mt][0] = sA[base];
                        a[mt][1] = sA[base + 8 * SA_STRIDE];
                        a[mt][2] = sA[base + 4];
                        a[mt][3] = sA[base + 8 * SA_STRIDE + 4];
                    }
#pragma unroll
                    for (int nt = 0; nt < 4; nt++) {
                        int n = wn * 32 + nt * 8 + g;
                        int krow = chunk * 128 + ks * 8 + tig;
                        float b[2];
                        b[0] = sB[krow * SB_STRIDE + n];
                        b[1] = sB[(krow + 4) * SB_STRIDE + n];
                        mma_tf32(acc[0][nt], a[0], b);
                        mma_tf32(acc[1][nt], a[1], b);
                    }
                }
                __syncthreads();
            }

            // ---- epilogue: bias + lane-pair exchange + gate update ----
            const bool ev = (lane & 1) == 0;
#pragma unroll
            for (int mt = 0; mt < 2; mt++) {
#pragma unroll
                for (int nt = 0; nt < 4; nt++) {
                    float4 z = acc[mt][nt];
                    int c0col = wn * 32 + nt * 8 + 2 * tig;
                    z.x += sBias[c0col];     // row r0, gate (2tig)&3
                    z.y += sBias[c0col + 1]; // row r0, gate +1
                    z.z += sBias[c0col];     // row r0+8
                    z.w += sBias[c0col + 1];
                    // even lane (cols = gates i,f of h): send its r1 (i,f),
                    // recv partner's r0 (g,o). Odd: symmetric.
                    float t0 = ev ? z.z : z.x;
                    float t1 = ev ? z.w : z.y;
                    float r0v = __shfl_xor_sync(0xFFFFFFFFu, t0, 1);
                    float r1v = __shfl_xor_sync(0xFFFFFFFFu, t1, 1);
                    float zi, zf, zg, zo;
                    int rowoff;
                    if (ev) { zi = z.x; zf = z.y; zg = r0v; zo = r1v; rowoff = 0; }
                    else    { zi = r0v; zf = r1v; zg = z.z; zo = z.w; rowoff = 8; }

                    int row = rb + wm * 32 + mt * 16 + g + rowoff;
                    int h_loc = (tig >> 1) + nt * 2 + wn * 8;
                    size_t gi = (size_t)row * H + hb + h_loc;

                    float ig = sigm_(zi);
                    float fg = sigm_(zf);
                    float gg = tanhf(zg);
                    float og = sigm_(zo);
                    float cn = fg * cptr[gi] + ig * gg;
                    cptr[gi] = cn;
                    hout[gi] = og * tanhf(cn);
                }
            }
        }

        grid_barrier(base_epoch + (++nbar));
    }

    // ---- dense head: blocks 0..3 (final h2 in g_h2[0]) ----
    if (bid < 4) {
        float* sWd1 = smem;
        float* sbd1 = smem + H2n * 50;
        float* sWd2 = sbd1 + 50;
        for (int i = tid; i < H2n * 50; i += NTHREADS) sWd1[i] = Wd1[i];
        if (tid < 50) { sbd1[tid] = bd1[tid]; sWd2[tid] = Wd2[tid]; }
        __syncthreads();
        if (tid < 128) {
            int b = bid * 128 + tid;
            const float* hrow = g_h2[0] + (size_t)b * H2n;
            float accj[50];
#pragma unroll
            for (int j = 0; j < 50; j++) accj[j] = 0.0f;
            for (int k = 0; k < H2n; k++) {
                float hv = hrow[k];
                const float* wrow = sWd1 + k * 50;
#pragma unroll
                for (int j = 0; j < 50; j++) accj[j] = fmaf(hv, wrow[j], accj[j]);
            }
            float o = bd2[0];
#pragma unroll
            for (int j = 0; j < 50; j++) o += (accj[j] + sbd1[j]) * sWd2[j];
            out[b] = o;
        }
    }
}

extern "C" void kernel_launch(void* const* d_in, const int* in_sizes, int n_in,
                              void* d_out, int out_size) {
    const float* inp = (const float*)d_in[0];
    const float* W1  = (const float*)d_in[1];
    const float* U1  = (const float*)d_in[2];
    const float* b1  = (const float*)d_in[3];
    const float* W2  = (const float*)d_in[4];
    const float* U2  = (const float*)d_in[5];
    const float* b2  = (const float*)d_in[6];
    const float* Wd1 = (const float*)d_in[7];
    const float* bd1 = (const float*)d_in[8];
    const float* Wd2 = (const float*)d_in[9];
    const float* bd2 = (const float*)d_in[10];

    static bool attr_done = false;
    if (!attr_done) {
        cudaFuncSetAttribute(lstm_mma,
                             cudaFuncAttributeMaxDynamicSharedMemorySize,
                             SMEM_BYTES);
        attr_done = true;
    }

    lstm_mma<<<NBLOCKS, NTHREADS, SMEM_BYTES>>>(
        inp, W1, U1, b1, W2, U2, b2, Wd1, bd1, Wd2, bd2, (float*)d_out);
}

// round 9
// speedup vs baseline: 3.1823x; 1.5421x over previous
#include <cuda_runtime.h>
#include <cstdint>

// Problem constants
#define Tn   512
#define Bn   512
#define Fn   128
#define H1n  256
#define H2n  128
#define KTOT 384

#define NBLOCKS  96
#define NTHREADS 256

// smem layout (floats).
//  B packed fragments: [ngrp(8)][ks(48)][lane(32)] x float2 = 24576 floats
//  A: [128][132] staging (4-pad)                             = 16896 floats
//  bias: 64
#define SA_STRIDE 132
#define OFF_B    0
#define OFF_A    24576
#define OFF_BIAS (OFF_A + 128 * SA_STRIDE)
#define SMEM_FLOATS (OFF_BIAS + 64)
#define SMEM_BYTES  (SMEM_FLOATS * 4)

// Persistent device state (c-state lives in registers now)
__device__ float g_h1[2][Bn * H1n];
__device__ float g_h2[2][Bn * H2n];
__device__ unsigned g_flags[NBLOCKS * 8];   // padded 32B/flag

__device__ __forceinline__ float sigm_(float x) { return 1.0f / (1.0f + expf(-x)); }

__device__ __forceinline__ float to_tf32(float x) {
    uint32_t y;
    asm("cvt.rna.tf32.f32 %0, %1;" : "=r"(y) : "f"(x));
    return __uint_as_float(y);
}

__device__ __forceinline__ void mma_tf32(float4& d, const float* a, const float* b) {
    asm volatile(
        "mma.sync.aligned.m16n8k8.row.col.f32.tf32.tf32.f32 "
        "{%0,%1,%2,%3}, {%4,%5,%6,%7}, {%8,%9}, {%0,%1,%2,%3};"
        : "+f"(d.x), "+f"(d.y), "+f"(d.z), "+f"(d.w)
        : "r"(__float_as_uint(a[0])), "r"(__float_as_uint(a[1])),
          "r"(__float_as_uint(a[2])), "r"(__float_as_uint(a[3])),
          "r"(__float_as_uint(b[0])), "r"(__float_as_uint(b[1])));
}

// Distributed barrier: each block publishes its progress; 96 threads poll all
// flags in parallel. No atomic serialization.
__device__ __forceinline__ void dist_barrier(unsigned target) {
    __syncthreads();
    if (threadIdx.x == 0) {
        __threadfence();
        *(volatile unsigned*)&g_flags[blockIdx.x * 8] = target;
    }
    if (threadIdx.x < NBLOCKS) {
        while ((int)(*(volatile unsigned*)&g_flags[threadIdx.x * 8] - target) < 0) { }
        __threadfence();
    }
    __syncthreads();
}

// ---------------------------------------------------------------------------
// Persistent tf32-MMA LSTM, pipelined.
//  blocks [0,64):  L1 — rb=(bid>>4)*128, hb=(bid&15)*16 of H1
//  blocks [64,96): L2 — rb=(lb>>3)*128,  hb=(lb&7)*16 of H2
// D[128,64] = A[128,384] x B[384,64] per block per step; K in 3 chunks of 128.
// Chunk c+1 globals prefetched to regs during chunk c MMA; L1's x chunk
// prefetched across the barrier. c-state in registers. z-col n = h*4+gate.
// ---------------------------------------------------------------------------
__global__ __launch_bounds__(NTHREADS, 1)
void lstm_mma(const float* __restrict__ inp,
              const float* __restrict__ W1, const float* __restrict__ U1,
              const float* __restrict__ b1,
              const float* __restrict__ W2, const float* __restrict__ U2,
              const float* __restrict__ b2,
              const float* __restrict__ Wd1, const float* __restrict__ bd1,
              const float* __restrict__ Wd2, const float* __restrict__ bd2,
              float* __restrict__ out) {
    extern __shared__ float smem[];
    float* sA = smem + OFF_A;
    float* sBias = smem + OFF_BIAS;
    const float2* sB2 = (const float2*)(smem + OFF_B);

    const int bid = blockIdx.x;
    const int tid = threadIdx.x;
    const int wid = tid >> 5;
    const int lane = tid & 31;
    const int g = lane >> 2;
    const int tig = lane & 3;
    const int wm = wid >> 1;
    const int wn = wid & 1;

    const bool is_l1 = (bid < 64);
    const float *Bw, *Bu, *bias;
    int Kx, H, rb, hb;
    if (is_l1) {
        Kx = Fn; H = H1n; Bw = W1; Bu = U1; bias = b1;
        rb = (bid >> 4) * 128;
        hb = (bid & 15) * 16;
    } else {
        int lb = bid - 64;
        Kx = H1n; H = H2n; Bw = W2; Bu = U2; bias = b2;
        rb = (lb >> 3) * 128;
        hb = (lb & 7) * 16;
    }
    const int ldb = 4 * H;

    // ---- one-time: weights -> packed fragment smem (tf32) ----
    // consumer: lane reads float2 {B[k,n], B[k+4,n]} at [ngrp=n>>3][ks=k>>3][lane=(n&7)*4+(k&3)]
    for (int idx = tid; idx < 64 * KTOT; idx += NTHREADS) {
        int n = idx / KTOT;
        int k = idx - n * KTOT;
        int j = (n & 3) * H + hb + (n >> 2);
        float v = (k < Kx) ? Bw[(size_t)k * ldb + j] : Bu[(size_t)(k - Kx) * ldb + j];
        int fi = (((n >> 3) * 48 + (k >> 3)) * 32 + (n & 7) * 4 + (k & 3)) * 2 + ((k >> 2) & 1);
        smem[OFF_B + fi] = to_tf32(v);
    }
    if (tid < 64) sBias[tid] = bias[(tid & 3) * H + hb + (tid >> 2)];

    // ---- one-time: zero h state ----
    {
        int gt = bid * NTHREADS + tid;
        int gs = NBLOCKS * NTHREADS;
        float* p1 = &g_h1[0][0];
        for (int k = gt; k < 2 * Bn * H1n; k += gs) p1[k] = 0.0f;
        float* p2 = &g_h2[0][0];
        for (int k = gt; k < 2 * Bn * H2n; k += gs) p2[k] = 0.0f;
    }

    unsigned base_epoch;
    {
        __shared__ unsigned s_base;
        if (tid == 0) s_base = *(volatile unsigned*)&g_flags[bid * 8];
        __syncthreads();
        base_epoch = s_base;
    }
    unsigned nbar = 0;

    float cst[2][4];     // register-resident c-state (fixed cells per thread)
#pragma unroll
    for (int mt = 0; mt < 2; mt++)
#pragma unroll
        for (int nt = 0; nt < 4; nt++) cst[mt][nt] = 0.0f;

    float4 pf[16];       // prefetch staging registers

    // prefetch L1 chunk0 (x at t=0) across the init barrier
    if (is_l1) {
#pragma unroll
        for (int i = 0; i < 16; i++) {
            int row = wid + 8 * i;
            pf[i] = __ldcg((const float4*)(inp + (size_t)Bn * Fn
                                           + (size_t)(rb + row) * Fn + lane * 4));
        }
    }

    dist_barrier(base_epoch + (++nbar));

    for (int t = 0; t < Tn; t++) {
        const int par = t & 1;
        const bool active = is_l1 ? (t < Tn - 1) : (t > 0);

        if (active) {
            const float* h1in = g_h1[par];
            float* hout;
            const float* csrc[3]; int clda[3], ckb[3];
            if (is_l1) {
                csrc[0] = nullptr; clda[0] = Fn;  ckb[0] = 0;     // preloaded x
                csrc[1] = h1in;    clda[1] = H1n; ckb[1] = 0;
                csrc[2] = h1in;    clda[2] = H1n; ckb[2] = 128;
                hout = g_h1[par ^ 1];
            } else {
                csrc[0] = h1in;      clda[0] = H1n; ckb[0] = 0;
                csrc[1] = h1in;      clda[1] = H1n; ckb[1] = 128;
                csrc[2] = g_h2[par]; clda[2] = H2n; ckb[2] = 0;
                hout = g_h2[par ^ 1];
            }

            if (!is_l1) {
#pragma unroll
                for (int i = 0; i < 16; i++) {
                    int row = wid + 8 * i;
                    pf[i] = __ldcg((const float4*)(csrc[0] + (size_t)(rb + row) * clda[0]
                                                   + ckb[0] + lane * 4));
                }
            }
            // store chunk0
#pragma unroll
            for (int i = 0; i < 16; i++) {
                int row = wid + 8 * i;
                float4 f = pf[i];
                f.x = to_tf32(f.x); f.y = to_tf32(f.y);
                f.z = to_tf32(f.z); f.w = to_tf32(f.w);
                *(float4*)(sA + row * SA_STRIDE + lane * 4) = f;
            }
            __syncthreads();

            float4 acc[2][4];
#pragma unroll
            for (int mt = 0; mt < 2; mt++)
#pragma unroll
                for (int nt = 0; nt < 4; nt++)
                    acc[mt][nt] = make_float4(0.f, 0.f, 0.f, 0.f);

#pragma unroll
            for (int chunk = 0; chunk < 3; chunk++) {
                if (chunk < 2) {
                    const float* src = csrc[chunk + 1];
                    int lda = clda[chunk + 1], kb = ckb[chunk + 1];
#pragma unroll
                    for (int i = 0; i < 16; i++) {
                        int row = wid + 8 * i;
                        pf[i] = __ldcg((const float4*)(src + (size_t)(rb + row) * lda
                                                       + kb + lane * 4));
                    }
                }
                // ---- 16 K-steps of m16n8k8 on smem chunk ----
#pragma unroll
                for (int ks = 0; ks < 16; ks++) {
                    float a[2][4];
#pragma unroll
                    for (int mt = 0; mt < 2; mt++) {
                        int base = (wm * 32 + mt * 16 + g) * SA_STRIDE + ks * 8 + tig;
                        a[mt][0] = sA[base];
                        a[mt][1] = sA[base + 8 * SA_STRIDE];
                        a[mt][2] = sA[base + 4];
                        a[mt][3] = sA[base + 8 * SA_STRIDE + 4];
                    }
                    int ks2 = chunk * 16 + ks;
#pragma unroll
                    for (int nt = 0; nt < 4; nt++) {
                        float2 b2 = sB2[((wn * 4 + nt) * 48 + ks2) * 32 + lane];
                        float b[2] = {b2.x, b2.y};
                        mma_tf32(acc[0][nt], a[0], b);
                        mma_tf32(acc[1][nt], a[1], b);
                    }
                }
                __syncthreads();
                if (chunk < 2) {
#pragma unroll
                    for (int i = 0; i < 16; i++) {
                        int row = wid + 8 * i;
                        float4 f = pf[i];
                        f.x = to_tf32(f.x); f.y = to_tf32(f.y);
                        f.z = to_tf32(f.z); f.w = to_tf32(f.w);
                        *(float4*)(sA + row * SA_STRIDE + lane * 4) = f;
                    }
                    __syncthreads();
                }
            }

            // ---- epilogue: bias + lane-pair exchange + gate update ----
            const bool ev = (lane & 1) == 0;
#pragma unroll
            for (int mt = 0; mt < 2; mt++) {
#pragma unroll
                for (int nt = 0; nt < 4; nt++) {
                    float4 z = acc[mt][nt];
                    int c0col = wn * 32 + nt * 8 + 2 * tig;
                    z.x += sBias[c0col];
                    z.y += sBias[c0col + 1];
                    z.z += sBias[c0col];
                    z.w += sBias[c0col + 1];
                    float t0 = ev ? z.z : z.x;
                    float t1 = ev ? z.w : z.y;
                    float r0v = __shfl_xor_sync(0xFFFFFFFFu, t0, 1);
                    float r1v = __shfl_xor_sync(0xFFFFFFFFu, t1, 1);
                    float zi, zf, zg, zo;
                    int rowoff;
                    if (ev) { zi = z.x; zf = z.y; zg = r0v; zo = r1v; rowoff = 0; }
                    else    { zi = r0v; zf = r1v; zg = z.z; zo = z.w; rowoff = 8; }

                    int row = rb + wm * 32 + mt * 16 + g + rowoff;
                    int h_loc = (tig >> 1) + nt * 2 + wn * 8;
                    size_t gi = (size_t)row * H + hb + h_loc;

                    float ig = sigm_(zi);
                    float fg = sigm_(zf);
                    float gg = tanhf(zg);
                    float og = sigm_(zo);
                    float cv = cst[mt][nt];
                    float cn = fg * cv + ig * gg;
                    cst[mt][nt] = cn;
                    hout[gi] = og * tanhf(cn);
                }
            }
        }

        // prefetch L1's next x chunk across the barrier
        if (is_l1 && (t + 1) < Tn - 1) {
            const float* xn = inp + (size_t)(t + 2) * Bn * Fn;
#pragma unroll
            for (int i = 0; i < 16; i++) {
                int row = wid + 8 * i;
                pf[i] = __ldcg((const float4*)(xn + (size_t)(rb + row) * Fn + lane * 4));
            }
        }

        dist_barrier(base_epoch + (++nbar));
    }

    // ---- dense head: blocks 0..3 (final h2 in g_h2[0]) ----
    if (bid < 4) {
        float* sWd1 = smem;
        float* sbd1 = smem + H2n * 50;
        float* sWd2 = sbd1 + 50;
        for (int i = tid; i < H2n * 50; i += NTHREADS) sWd1[i] = Wd1[i];
        if (tid < 50) { sbd1[tid] = bd1[tid]; sWd2[tid] = Wd2[tid]; }
        __syncthreads();
        if (tid < 128) {
            int b = bid * 128 + tid;
            const float* hrow = g_h2[0] + (size_t)b * H2n;
            float accj[50];
#pragma unroll
            for (int j = 0; j < 50; j++) accj[j] = 0.0f;
            for (int k = 0; k < H2n; k++) {
                float hv = hrow[k];
                const float* wrow = sWd1 + k * 50;
#pragma unroll
                for (int j = 0; j < 50; j++) accj[j] = fmaf(hv, wrow[j], accj[j]);
            }
            float o = bd2[0];
#pragma unroll
            for (int j = 0; j < 50; j++) o += (accj[j] + sbd1[j]) * sWd2[j];
            out[b] = o;
        }
    }
}

extern "C" void kernel_launch(void* const* d_in, const int* in_sizes, int n_in,
                              void* d_out, int out_size) {
    const float* inp = (const float*)d_in[0];
    const float* W1  = (const float*)d_in[1];
    const float* U1  = (const float*)d_in[2];
    const float* b1  = (const float*)d_in[3];
    const float* W2  = (const float*)d_in[4];
    const float* U2  = (const float*)d_in[5];
    const float* b2  = (const float*)d_in[6];
    const float* Wd1 = (const float*)d_in[7];
    const float* bd1 = (const float*)d_in[8];
    const float* Wd2 = (const float*)d_in[9];
    const float* bd2 = (const float*)d_in[10];

    static bool attr_done = false;
    if (!attr_done) {
        cudaFuncSetAttribute(lstm_mma,
                             cudaFuncAttributeMaxDynamicSharedMemorySize,
                             SMEM_BYTES);
        attr_done = true;
    }

    lstm_mma<<<NBLOCKS, NTHREADS, SMEM_BYTES>>>(
        inp, W1, U1, b1, W2, U2, b2, Wd1, bd1, Wd2, bd2, (float*)d_out);
}